// round 12
// baseline (speedup 1.0000x reference)
#include <cuda_runtime.h>

#define N_NODESC 100000
#define N_EDGESC 3200000
#define N_GRAPHSC 1024
#define HIDC 64
#define NCLS 21
#define MAXDEG 128                                // Poisson(32): P(deg>128) ~ 1e-40
#define PACK_SHIFT 42
#define PACK_MASK ((1ULL << PACK_SHIFT) - 1ULL)
#define FIX_SCALE 4194304.0f                      // 2^22
#define FIX_BIAS (1 << 30)

// ---------------- scratch (device globals; zero-init at load) ----------------
// Invariant: g_pack, g_gcnt, g_pooled are ZERO at kernel_launch entry.
// True at load time; each run restores it for the next (deterministic).
__device__ unsigned long long g_pack[N_NODESC];   // {deg/cursor:22 | biased fixed sum x:42}
__device__ int                g_adj[N_NODESC * MAXDEG];  // static-bucket CSR
__device__ float2             g_s1[N_NODESC];     // per node {a1 = mean x[src], x}
__device__ float2             g_a2[32 * N_NODESC];// layer-2 mean-agg, PAIR-major [pair][node]
__device__ float4             g_pooled[N_GRAPHSC * 16];
__device__ float              g_gcnt[N_GRAPHSC];

// packed f32x2 helpers (sm_103a: FFMA2 only via PTX)
#define FMA2(acc, m, w) asm("fma.rn.f32x2 %0, %1, %2, %0;" : "+d"(acc) : "d"(m), "d"(w))
__device__ __forceinline__ double pack2(float v) {
    double d;
    asm("mov.b64 %0, {%1, %1};" : "=d"(d) : "r"(__float_as_uint(v)));
    return d;
}

// PDL: wait for predecessor kernel completion (no-op when launched normally)
__device__ __forceinline__ void gdc_wait() {
    asm volatile("griddepcontrol.wait;" ::: "memory");
}

// block-local dtype probe: int64 small values => odd 32-bit words all zero
__device__ __forceinline__ bool detect32(const int* p, int* s_flag) {
    if (threadIdx.x < 32) {
        int acc = 0;
        for (int j = threadIdx.x; j < 64; j += 32) acc |= p[2 * j + 1];
        acc = __reduce_or_sync(0xffffffffu, acc);
        if (threadIdx.x == 0) *s_flag = (acc != 0);
    }
    __syncthreads();
    return *s_flag != 0;
}

__device__ __forceinline__ int load_idx(const void* p, long i, bool is32) {
    if (is32) return ((const int*)p)[i];
    return (int)((const long long*)p)[i];
}

// ---------------- scatter: static-bucket CSR + fused scalar agg (one u64 atomic/edge) ----
// First kernel of the chain. Also restores g_gcnt / g_pooled for this run.
__global__ void k_scatter(const void* eptr, const float* __restrict__ x) {
    __shared__ int s_e32;
    bool e32 = detect32((const int*)eptr, &s_e32);
    int gid = blockIdx.x * blockDim.x + threadIdx.x;
    if (gid < N_GRAPHSC) g_gcnt[gid] = 0.f;
    if (gid < N_GRAPHSC * 16) g_pooled[gid] = make_float4(0.f, 0.f, 0.f, 0.f);
    long e = (long)gid * 4;
    if (e >= N_EDGESC) return;
    int s0, s1i, s2, s3, d0, d1, d2, d3;
    if (e32) {
        int4 sv = *(const int4*)((const int*)eptr + e);
        int4 dv = *(const int4*)((const int*)eptr + N_EDGESC + e);
        s0 = sv.x; s1i = sv.y; s2 = sv.z; s3 = sv.w;
        d0 = dv.x; d1 = dv.y; d2 = dv.z; d3 = dv.w;
    } else {
        const longlong2* sp_ = (const longlong2*)((const long long*)eptr + e);
        const longlong2* dp_ = (const longlong2*)((const long long*)eptr + N_EDGESC + e);
        longlong2 a = sp_[0], bq = sp_[1], cq = dp_[0], dq = dp_[1];
        s0 = (int)a.x; s1i = (int)a.y; s2 = (int)bq.x; s3 = (int)bq.y;
        d0 = (int)cq.x; d1 = (int)cq.y; d2 = (int)dq.x; d3 = (int)dq.y;
    }
    float x0 = __ldg(&x[s0]), x1 = __ldg(&x[s1i]), x2 = __ldg(&x[s2]), x3 = __ldg(&x[s3]);
    unsigned long long a0 = (1ULL << PACK_SHIFT) |
        (unsigned long long)(unsigned)(__float2int_rn(x0 * FIX_SCALE) + FIX_BIAS);
    unsigned long long a1 = (1ULL << PACK_SHIFT) |
        (unsigned long long)(unsigned)(__float2int_rn(x1 * FIX_SCALE) + FIX_BIAS);
    unsigned long long a2 = (1ULL << PACK_SHIFT) |
        (unsigned long long)(unsigned)(__float2int_rn(x2 * FIX_SCALE) + FIX_BIAS);
    unsigned long long a3 = (1ULL << PACK_SHIFT) |
        (unsigned long long)(unsigned)(__float2int_rn(x3 * FIX_SCALE) + FIX_BIAS);
    unsigned c0 = (unsigned)(atomicAdd(&g_pack[d0], a0) >> PACK_SHIFT);
    unsigned c1 = (unsigned)(atomicAdd(&g_pack[d1], a1) >> PACK_SHIFT);
    unsigned c2 = (unsigned)(atomicAdd(&g_pack[d2], a2) >> PACK_SHIFT);
    unsigned c3 = (unsigned)(atomicAdd(&g_pack[d3], a3) >> PACK_SHIFT);
    if (c0 < MAXDEG) g_adj[d0 * MAXDEG + c0] = s0;
    if (c1 < MAXDEG) g_adj[d1 * MAXDEG + c1] = s1i;
    if (c2 < MAXDEG) g_adj[d2 * MAXDEG + c2] = s2;
    if (c3 < MAXDEG) g_adj[d3 * MAXDEG + c3] = s3;
}

// ---------------- finalize s1 + warp-aggregated graph counts ----------------
__global__ void k_s1(const float* __restrict__ x, const void* bptr) {
    __shared__ int s_b32;
    bool b32 = detect32((const int*)bptr, &s_b32);
    int n = blockIdx.x * blockDim.x + threadIdx.x;
    bool valid = (n < N_NODESC);
    int g = 0;
    float xv = 0.f;
    if (valid) { g = load_idx(bptr, n, b32); xv = __ldg(&x[n]); }   // inputs: pre-wait
    gdc_wait();
    unsigned mask = __ballot_sync(0xffffffffu, valid);
    if (valid) {
        unsigned long long p = g_pack[n];
        int deg = (int)(p >> PACK_SHIFT);
        long long sfx = (long long)(p & PACK_MASK) - (long long)deg * (long long)FIX_BIAS;
        float a1 = ((float)sfx * (1.0f / FIX_SCALE)) / fmaxf((float)deg, 1.0f);
        g_s1[n] = make_float2(a1, xv);
        // warp-aggregated gcnt (batch sorted => usually uniform)
        int leader = __ffs(mask) - 1;
        int g0 = __shfl_sync(mask, g, leader);
        bool uni = __all_sync(mask, g == g0);
        if (uni) {
            if ((threadIdx.x & 31) == leader)
                atomicAdd(&g_gcnt[g0], (float)__popc(mask));
        } else {
            atomicAdd(&g_gcnt[g], 1.0f);
        }
    }
}

// ---------------- sweep 2: mean-aggregate h1 (warp per node, recomputed scalars) ----------------
__global__ void k_sweep2(const float* __restrict__ W1l, const float* __restrict__ b1,
                         const float* __restrict__ W1r) {
    int n = (blockIdx.x * blockDim.x + threadIdx.x) >> 5;
    int lane = threadIdx.x & 31;
    float2 wl = __ldg((const float2*)W1l + lane);   // weights: pre-wait prologue
    float2 wr = __ldg((const float2*)W1r + lane);
    float2 bb = __ldg((const float2*)b1 + lane);
    gdc_wait();
    if (n >= N_NODESC) return;
    int deg = (int)(g_pack[n] >> PACK_SHIFT);
    if (deg > MAXDEG) deg = MAXDEG;
    const int* adjn = g_adj + n * MAXDEG;           // 512B-aligned slab
    float2 acc = make_float2(0.f, 0.f);
    int base = 0;
    for (; base + 32 <= deg; base += 32) {          // full chunks, unguarded
        float2 sv = g_s1[adjn[base + lane]];
#pragma unroll 8
        for (int j = 0; j < 32; j++) {
            float a1 = __shfl_sync(0xffffffffu, sv.x, j);
            float xv = __shfl_sync(0xffffffffu, sv.y, j);
            acc.x += fmaxf(fmaf(a1, wl.x, fmaf(xv, wr.x, bb.x)), 0.f);
            acc.y += fmaxf(fmaf(a1, wl.y, fmaf(xv, wr.y, bb.y)), 0.f);
        }
    }
    if (base < deg) {                               // tail
        int m = deg - base;
        float2 sv = make_float2(0.f, 0.f);
        if (lane < m) sv = g_s1[adjn[base + lane]];
        for (int j = 0; j < m; j++) {
            float a1 = __shfl_sync(0xffffffffu, sv.x, j);
            float xv = __shfl_sync(0xffffffffu, sv.y, j);
            acc.x += fmaxf(fmaf(a1, wl.x, fmaf(xv, wr.x, bb.x)), 0.f);
            acc.y += fmaxf(fmaf(a1, wl.y, fmaf(xv, wr.y, bb.y)), 0.f);
        }
    }
    float inv = 1.0f / fmaxf((float)deg, 1.0f);
    g_a2[(long)lane * N_NODESC + n] = make_float2(acc.x * inv, acc.y * inv);
}

// ---------------- layer-2 dense (f32x2) + relu + pooling; re-zeroes g_pack ----------------
// 320 threads = 160 nodes x 2 halves; each thread computes 32 of the 64 outputs.
__global__ void __launch_bounds__(320) k_h2pool(
        const void* bptr,
        const float* __restrict__ W1l, const float* __restrict__ b1, const float* __restrict__ W1r,
        const float* __restrict__ W2l, const float* __restrict__ b2, const float* __restrict__ W2r) {
    __shared__ __align__(16) float sWl[HIDC * HIDC];
    __shared__ __align__(16) float sWr[HIDC * HIDC];
    __shared__ float sW1[3][HIDC];
    __shared__ int s_b32;
    bool b32 = detect32((const int*)bptr, &s_b32);
    int tid = threadIdx.x;
    // prologue: stage 32KB of weights while sweep2 drains
    for (int i = tid; i < HIDC * HIDC; i += 320) { sWl[i] = W2l[i]; sWr[i] = W2r[i]; }
    if (tid < HIDC) { sW1[0][tid] = W1l[tid]; sW1[1][tid] = W1r[tid]; sW1[2][tid] = b1[tid]; }
    int half = (tid >= 160) ? 1 : 0;                 // output half
    int nl = tid - half * 160;
    int n = blockIdx.x * 160 + nl;                   // exact: 625*160 = 100000
    int g = load_idx(bptr, n, b32);
    int wofs = half * 32;                            // output column offset (floats)
    double acc2[16];
    const double* b2d = (const double*)b2 + half * 16;
#pragma unroll
    for (int q = 0; q < 16; q++) acc2[q] = __ldg(&b2d[q]);
    __syncthreads();
    gdc_wait();                                      // sweep2 (reads g_pack) must be done
    if (half == 0) g_pack[n] = 0ULL;                 // restore invariant for next run
    float2 s1 = g_s1[n];
    float a1 = s1.x, xv = s1.y;

#pragma unroll 1
    for (int p = 0; p < 32; p++) {
        float2 a2v = g_a2[(long)p * N_NODESC + n];   // pair-major: coalesced read
        int k0 = 2 * p, k1 = 2 * p + 1;
        float h1a = fmaxf(a1 * sW1[0][k0] + xv * sW1[1][k0] + sW1[2][k0], 0.f);
        float h1b = fmaxf(a1 * sW1[0][k1] + xv * sW1[1][k1] + sW1[2][k1], 0.f);
        double pa = pack2(a2v.x), pb = pack2(a2v.y);
        double ph = pack2(h1a),   pi = pack2(h1b);
        const double2* wl0 = (const double2*)(sWl + k0 * HIDC + wofs);
        const double2* wl1 = (const double2*)(sWl + k1 * HIDC + wofs);
        const double2* wr0 = (const double2*)(sWr + k0 * HIDC + wofs);
        const double2* wr1 = (const double2*)(sWr + k1 * HIDC + wofs);
#pragma unroll
        for (int jb = 0; jb < 8; jb++) {
            double2 w0 = wl0[jb], w1 = wl1[jb], u0 = wr0[jb], u1 = wr1[jb];
            FMA2(acc2[2 * jb],     pa, w0.x); FMA2(acc2[2 * jb + 1], pa, w0.y);
            FMA2(acc2[2 * jb],     pb, w1.x); FMA2(acc2[2 * jb + 1], pb, w1.y);
            FMA2(acc2[2 * jb],     ph, u0.x); FMA2(acc2[2 * jb + 1], ph, u0.y);
            FMA2(acc2[2 * jb],     pi, u1.x); FMA2(acc2[2 * jb + 1], pi, u1.y);
        }
    }

    // relu + pooling: warp covers 32 consecutive nodes within one half
    bool uni = __all_sync(0xffffffffu, g == __shfl_sync(0xffffffffu, g, 0));
    float* pooledf = (float*)g_pooled;
#pragma unroll
    for (int jb = 0; jb < 8; jb++) {
        double p0 = acc2[2 * jb], p1 = acc2[2 * jb + 1];
        float4 v;
        v.x = fmaxf(__int_as_float(__double2loint(p0)), 0.f);
        v.y = fmaxf(__int_as_float(__double2hiint(p0)), 0.f);
        v.z = fmaxf(__int_as_float(__double2loint(p1)), 0.f);
        v.w = fmaxf(__int_as_float(__double2hiint(p1)), 0.f);
        if (uni) {
            for (int o = 16; o > 0; o >>= 1) {
                v.x += __shfl_xor_sync(0xffffffffu, v.x, o);
                v.y += __shfl_xor_sync(0xffffffffu, v.y, o);
                v.z += __shfl_xor_sync(0xffffffffu, v.z, o);
                v.w += __shfl_xor_sync(0xffffffffu, v.w, o);
            }
            if ((tid & 31) == 0)
                atomicAdd((float4*)(pooledf + g * HIDC + wofs + 4 * jb), v);
        } else {
            atomicAdd((float4*)(pooledf + g * HIDC + wofs + 4 * jb), v);
        }
    }
}

// ---------------- classifier ----------------
__global__ void k_cls(const float* __restrict__ Wc, const float* __restrict__ bc,
                      float* __restrict__ out) {
    __shared__ float sp[HIDC];
    int g = blockIdx.x, t = threadIdx.x;   // 32 threads
    float bias = (t < NCLS) ? __ldg(&bc[t]) : 0.f;   // pre-wait
    gdc_wait();
    float invg = 1.0f / fmaxf(g_gcnt[g], 1.0f);
    const float* pooledf = (const float*)g_pooled;
    sp[t] = pooledf[g * HIDC + t] * invg;
    sp[t + 32] = pooledf[g * HIDC + 32 + t] * invg;
    __syncwarp();
    if (t < NCLS) {
        float a = bias;
#pragma unroll
        for (int j = 0; j < HIDC; j++) a += sp[j] * __ldg(&Wc[j * NCLS + t]);
        out[g * NCLS + t] = a;
    }
}

// ---------------- launch helpers (PDL) ----------------
template <typename... Args>
static void launch_pdl(void (*fn)(Args...), dim3 grid, dim3 block, Args... args) {
    cudaLaunchConfig_t cfg = {};
    cfg.gridDim = grid;
    cfg.blockDim = block;
    cfg.dynamicSmemBytes = 0;
    cfg.stream = 0;
    cudaLaunchAttribute at[1];
    at[0].id = cudaLaunchAttributeProgrammaticStreamSerialization;
    at[0].val.programmaticStreamSerializationAllowed = 1;
    cfg.attrs = at;
    cfg.numAttrs = 1;
    cudaLaunchKernelEx(&cfg, fn, args...);
}

extern "C" void kernel_launch(void* const* d_in, const int* in_sizes, int n_in,
                              void* d_out, int out_size) {
    const float* x   = (const float*)d_in[0];
    const void*  ei  = d_in[1];
    const void*  bt  = d_in[2];
    const float* W1l = (const float*)d_in[3];
    const float* b1  = (const float*)d_in[4];
    const float* W1r = (const float*)d_in[5];
    const float* W2l = (const float*)d_in[6];
    const float* b2  = (const float*)d_in[7];
    const float* W2r = (const float*)d_in[8];
    const float* Wc  = (const float*)d_in[9];
    const float* bc  = (const float*)d_in[10];
    float* out = (float*)d_out;

    k_scatter<<<N_EDGESC / 1024, 256>>>(ei, x);
    launch_pdl(k_s1, dim3((N_NODESC + 255) / 256), dim3(256), x, (const void*)bt);
    launch_pdl(k_sweep2, dim3(N_NODESC / 8), dim3(256), W1l, b1, W1r);
    launch_pdl(k_h2pool, dim3(N_NODESC / 160), dim3(320), (const void*)bt, W1l, b1, W1r, W2l, b2, W2r);
    launch_pdl(k_cls, dim3(N_GRAPHSC), dim3(32), Wc, bc, out);
}

// round 13
// speedup vs baseline: 1.4309x; 1.4309x over previous
#include <cuda_runtime.h>

#define N_NODESC 100000
#define N_EDGESC 3200000
#define N_GRAPHSC 1024
#define HIDC 64
#define NCLS 21
#define MAXDEG 128                                // Poisson(32): P(deg>128) ~ 1e-40
#define PACK_SHIFT 42
#define PACK_MASK ((1ULL << PACK_SHIFT) - 1ULL)
#define FIX_SCALE 4194304.0f                      // 2^22
#define FIX_BIAS (1 << 30)
#define SAS 72                                    // smem tile row stride (words): 8c+r bank bijection
#define H2_BLKS ((N_NODESC + 63) / 64)            // 1563

// ---------------- scratch (device globals; zero-init at load) ----------------
// Invariant: g_pack, g_gcnt, g_pooled are ZERO at kernel_launch entry.
// True at load time; each run restores it for the next (deterministic).
__device__ unsigned long long g_pack[N_NODESC];   // {deg/cursor:22 | biased fixed sum x:42}
__device__ int                g_adj[N_NODESC * MAXDEG];  // static-bucket CSR
__device__ float2             g_s1[N_NODESC];     // per node {a1 = mean x[src], x}
__device__ float2             g_a2[32 * N_NODESC];// layer-2 mean-agg, PAIR-major [pair][node]
__device__ float4             g_pooled[N_GRAPHSC * 16];
__device__ float              g_gcnt[N_GRAPHSC];

// PDL: wait for predecessor kernel completion (no-op when launched normally)
__device__ __forceinline__ void gdc_wait() {
    asm volatile("griddepcontrol.wait;" ::: "memory");
}

// block-local dtype probe: int64 small values => odd 32-bit words all zero
__device__ __forceinline__ bool detect32(const int* p, int* s_flag) {
    if (threadIdx.x < 32) {
        int acc = 0;
        for (int j = threadIdx.x; j < 64; j += 32) acc |= p[2 * j + 1];
        acc = __reduce_or_sync(0xffffffffu, acc);
        if (threadIdx.x == 0) *s_flag = (acc != 0);
    }
    __syncthreads();
    return *s_flag != 0;
}

__device__ __forceinline__ int load_idx(const void* p, long i, bool is32) {
    if (is32) return ((const int*)p)[i];
    return (int)((const long long*)p)[i];
}

__device__ __forceinline__ unsigned tf32cvt(float f) {
    unsigned u;
    asm("cvt.rna.tf32.f32 %0, %1;" : "=r"(u) : "f"(f));
    return u;
}

#define MMA_TF32(d, a0, a1, b0) \
    asm volatile("mma.sync.aligned.m16n8k4.row.col.f32.tf32.tf32.f32 " \
        "{%0,%1,%2,%3}, {%4,%5}, {%6}, {%0,%1,%2,%3};" \
        : "+f"(d[0]), "+f"(d[1]), "+f"(d[2]), "+f"(d[3]) \
        : "r"(a0), "r"(a1), "r"(b0))

// ---------------- scatter: static-bucket CSR + fused scalar agg (one u64 atomic/edge) ----
__global__ void k_scatter(const void* eptr, const float* __restrict__ x) {
    __shared__ int s_e32;
    bool e32 = detect32((const int*)eptr, &s_e32);
    int gid = blockIdx.x * blockDim.x + threadIdx.x;
    if (gid < N_GRAPHSC) g_gcnt[gid] = 0.f;
    if (gid < N_GRAPHSC * 16) g_pooled[gid] = make_float4(0.f, 0.f, 0.f, 0.f);
    long e = (long)gid * 4;
    if (e >= N_EDGESC) return;
    int s0, s1i, s2, s3, d0, d1, d2, d3;
    if (e32) {
        int4 sv = *(const int4*)((const int*)eptr + e);
        int4 dv = *(const int4*)((const int*)eptr + N_EDGESC + e);
        s0 = sv.x; s1i = sv.y; s2 = sv.z; s3 = sv.w;
        d0 = dv.x; d1 = dv.y; d2 = dv.z; d3 = dv.w;
    } else {
        const longlong2* sp_ = (const longlong2*)((const long long*)eptr + e);
        const longlong2* dp_ = (const longlong2*)((const long long*)eptr + N_EDGESC + e);
        longlong2 a = sp_[0], bq = sp_[1], cq = dp_[0], dq = dp_[1];
        s0 = (int)a.x; s1i = (int)a.y; s2 = (int)bq.x; s3 = (int)bq.y;
        d0 = (int)cq.x; d1 = (int)cq.y; d2 = (int)dq.x; d3 = (int)dq.y;
    }
    float x0 = __ldg(&x[s0]), x1 = __ldg(&x[s1i]), x2 = __ldg(&x[s2]), x3 = __ldg(&x[s3]);
    unsigned long long a0 = (1ULL << PACK_SHIFT) |
        (unsigned long long)(unsigned)(__float2int_rn(x0 * FIX_SCALE) + FIX_BIAS);
    unsigned long long a1 = (1ULL << PACK_SHIFT) |
        (unsigned long long)(unsigned)(__float2int_rn(x1 * FIX_SCALE) + FIX_BIAS);
    unsigned long long a2 = (1ULL << PACK_SHIFT) |
        (unsigned long long)(unsigned)(__float2int_rn(x2 * FIX_SCALE) + FIX_BIAS);
    unsigned long long a3 = (1ULL << PACK_SHIFT) |
        (unsigned long long)(unsigned)(__float2int_rn(x3 * FIX_SCALE) + FIX_BIAS);
    unsigned c0 = (unsigned)(atomicAdd(&g_pack[d0], a0) >> PACK_SHIFT);
    unsigned c1 = (unsigned)(atomicAdd(&g_pack[d1], a1) >> PACK_SHIFT);
    unsigned c2 = (unsigned)(atomicAdd(&g_pack[d2], a2) >> PACK_SHIFT);
    unsigned c3 = (unsigned)(atomicAdd(&g_pack[d3], a3) >> PACK_SHIFT);
    if (c0 < MAXDEG) g_adj[d0 * MAXDEG + c0] = s0;
    if (c1 < MAXDEG) g_adj[d1 * MAXDEG + c1] = s1i;
    if (c2 < MAXDEG) g_adj[d2 * MAXDEG + c2] = s2;
    if (c3 < MAXDEG) g_adj[d3 * MAXDEG + c3] = s3;
}

// ---------------- finalize s1 + warp-aggregated graph counts ----------------
__global__ void k_s1(const float* __restrict__ x, const void* bptr) {
    __shared__ int s_b32;
    bool b32 = detect32((const int*)bptr, &s_b32);
    int n = blockIdx.x * blockDim.x + threadIdx.x;
    bool valid = (n < N_NODESC);
    int g = 0;
    float xv = 0.f;
    if (valid) { g = load_idx(bptr, n, b32); xv = __ldg(&x[n]); }   // inputs: pre-wait
    gdc_wait();
    unsigned mask = __ballot_sync(0xffffffffu, valid);
    if (valid) {
        unsigned long long p = g_pack[n];
        int deg = (int)(p >> PACK_SHIFT);
        long long sfx = (long long)(p & PACK_MASK) - (long long)deg * (long long)FIX_BIAS;
        float a1 = ((float)sfx * (1.0f / FIX_SCALE)) / fmaxf((float)deg, 1.0f);
        g_s1[n] = make_float2(a1, xv);
        int leader = __ffs(mask) - 1;
        int g0 = __shfl_sync(mask, g, leader);
        bool uni = __all_sync(mask, g == g0);
        if (uni) {
            if ((threadIdx.x & 31) == leader)
                atomicAdd(&g_gcnt[g0], (float)__popc(mask));
        } else {
            atomicAdd(&g_gcnt[g], 1.0f);
        }
    }
}

// ---------------- sweep 2: mean-aggregate h1 (warp per node, recomputed scalars) ----------------
__global__ void k_sweep2(const float* __restrict__ W1l, const float* __restrict__ b1,
                         const float* __restrict__ W1r) {
    int n = (blockIdx.x * blockDim.x + threadIdx.x) >> 5;
    int lane = threadIdx.x & 31;
    float2 wl = __ldg((const float2*)W1l + lane);   // weights: pre-wait prologue
    float2 wr = __ldg((const float2*)W1r + lane);
    float2 bb = __ldg((const float2*)b1 + lane);
    gdc_wait();
    if (n >= N_NODESC) return;
    int deg = (int)(g_pack[n] >> PACK_SHIFT);
    if (deg > MAXDEG) deg = MAXDEG;
    const int* adjn = g_adj + n * MAXDEG;           // 512B-aligned slab
    float2 acc = make_float2(0.f, 0.f);
    int base = 0;
    for (; base + 32 <= deg; base += 32) {          // full chunks, unguarded
        float2 sv = g_s1[adjn[base + lane]];
#pragma unroll 8
        for (int j = 0; j < 32; j++) {
            float a1 = __shfl_sync(0xffffffffu, sv.x, j);
            float xv = __shfl_sync(0xffffffffu, sv.y, j);
            acc.x += fmaxf(fmaf(a1, wl.x, fmaf(xv, wr.x, bb.x)), 0.f);
            acc.y += fmaxf(fmaf(a1, wl.y, fmaf(xv, wr.y, bb.y)), 0.f);
        }
    }
    if (base < deg) {                               // tail
        int m = deg - base;
        float2 sv = make_float2(0.f, 0.f);
        if (lane < m) sv = g_s1[adjn[base + lane]];
        for (int j = 0; j < m; j++) {
            float a1 = __shfl_sync(0xffffffffu, sv.x, j);
            float xv = __shfl_sync(0xffffffffu, sv.y, j);
            acc.x += fmaxf(fmaf(a1, wl.x, fmaf(xv, wr.x, bb.x)), 0.f);
            acc.y += fmaxf(fmaf(a1, wl.y, fmaf(xv, wr.y, bb.y)), 0.f);
        }
    }
    float inv = 1.0f / fmaxf((float)deg, 1.0f);
    g_a2[(long)lane * N_NODESC + n] = make_float2(acc.x * inv, acc.y * inv);
}

// ---------------- layer-2 dense via tf32 mma.sync + relu + segmented pooling ----------------
// 128 threads / 64 nodes per block. Two K-phases: (a2 x W2l), then (h1 x W2r).
__global__ void __launch_bounds__(128) k_h2pool(
        const void* bptr,
        const float* __restrict__ W1l, const float* __restrict__ b1, const float* __restrict__ W1r,
        const float* __restrict__ W2l, const float* __restrict__ b2, const float* __restrict__ W2r) {
    __shared__ unsigned sA[64 * SAS];   // A tile: [k][node] tf32; epilogue reused as D [node][out] f32
    __shared__ unsigned sB[64 * SAS];   // B tile: [k][out]  tf32
    __shared__ float sW1[3 * HIDC];
    __shared__ int   sG[64];
    __shared__ int   s_b32;
    bool b32 = detect32((const int*)bptr, &s_b32);
    const int t = threadIdx.x;
    const int nb = blockIdx.x * 64;
    const int w = t >> 5, lane = t & 31;
    const int r = lane >> 2, cc = lane & 3;         // fragment row / k-col within group

    // ---- prologue (inputs only, overlap predecessor tail) ----
    if (t < HIDC) { sW1[t] = W1l[t]; sW1[HIDC + t] = W1r[t]; sW1[2 * HIDC + t] = b1[t]; }
    if (t < 64) {
        int n = nb + t;
        sG[t] = (n < N_NODESC) ? load_idx(bptr, n, b32) : -1;
    }
#pragma unroll
    for (int c = 0; c < 32; c++) {                  // stage W2l -> sB (tf32)
        int idx = c * 128 + t;
        sB[(idx >> 6) * SAS + (idx & 63)] = tf32cvt(__ldg(&W2l[idx]));
    }
    float acc[8][4];
#pragma unroll
    for (int nt = 0; nt < 8; nt++) {                // bias init: acc[(node r / r+8)][col 8nt+2cc(+1)]
        float bA = __ldg(&b2[nt * 8 + 2 * cc]);
        float bB = __ldg(&b2[nt * 8 + 2 * cc + 1]);
        acc[nt][0] = bA; acc[nt][1] = bB; acc[nt][2] = bA; acc[nt][3] = bB;
    }
    __syncthreads();
    gdc_wait();                                      // sweep2 (and transitively s1) done
    int gp = blockIdx.x * 128 + t;
    if (gp < N_NODESC) g_pack[gp] = 0ULL;            // restore invariant for next run

    // ---- phase 1: A = a2 (features 0..63) ----
#pragma unroll
    for (int c = 0; c < 16; c++) {
        int idx = c * 128 + t;
        int p = idx >> 6, n = idx & 63;
        float2 v = (nb + n < N_NODESC) ? g_a2[(long)p * N_NODESC + nb + n] : make_float2(0.f, 0.f);
        sA[(2 * p) * SAS + n] = tf32cvt(v.x);
        sA[(2 * p + 1) * SAS + n] = tf32cvt(v.y);
    }
    __syncthreads();
#pragma unroll
    for (int kt = 0; kt < 16; kt++) {
        int ka = kt * 4 + cc;
        unsigned a0 = sA[ka * SAS + w * 16 + r];
        unsigned a1 = sA[ka * SAS + w * 16 + r + 8];
#pragma unroll
        for (int nt = 0; nt < 8; nt++) {
            unsigned b0 = sB[ka * SAS + nt * 8 + r];
            MMA_TF32(acc[nt], a0, a1, b0);
        }
    }
    __syncthreads();

    // ---- phase 2: A = h1 (recomputed), B = W2r ----
#pragma unroll
    for (int c = 0; c < 32; c++) {
        int idx = c * 128 + t;
        sB[(idx >> 6) * SAS + (idx & 63)] = tf32cvt(__ldg(&W2r[idx]));
    }
    {
        int n = t & 63;
        int fh = (t >> 6) * 32;
        int nn = nb + n; if (nn >= N_NODESC) nn = N_NODESC - 1;
        float2 s1v = g_s1[nn];
#pragma unroll
        for (int f0 = 0; f0 < 32; f0++) {
            int f = fh + f0;
            float h = fmaxf(fmaf(s1v.x, sW1[f], fmaf(s1v.y, sW1[HIDC + f], sW1[2 * HIDC + f])), 0.f);
            sA[f * SAS + n] = tf32cvt(h);
        }
    }
    __syncthreads();
#pragma unroll
    for (int kt = 0; kt < 16; kt++) {
        int ka = kt * 4 + cc;
        unsigned a0 = sA[ka * SAS + w * 16 + r];
        unsigned a1 = sA[ka * SAS + w * 16 + r + 8];
#pragma unroll
        for (int nt = 0; nt < 8; nt++) {
            unsigned b0 = sB[ka * SAS + nt * 8 + r];
            MMA_TF32(acc[nt], a0, a1, b0);
        }
    }
    __syncthreads();

    // ---- epilogue: relu -> D tile in sA as [node][out] ----
    float* sD = (float*)sA;
#pragma unroll
    for (int nt = 0; nt < 8; nt++) {
        int col = nt * 8 + 2 * cc;
        sD[(w * 16 + r) * SAS + col]         = fmaxf(acc[nt][0], 0.f);
        sD[(w * 16 + r) * SAS + col + 1]     = fmaxf(acc[nt][1], 0.f);
        sD[(w * 16 + r + 8) * SAS + col]     = fmaxf(acc[nt][2], 0.f);
        sD[(w * 16 + r + 8) * SAS + col + 1] = fmaxf(acc[nt][3], 0.f);
    }
    __syncthreads();

    // ---- segmented pooling: thread t: column t&63, rows half*32..+31 ----
    {
        int col = t & 63;
        int r0 = (t >> 6) * 32;
        float* pooledf = (float*)g_pooled;
        float run = 0.f;
        int cg = sG[r0];
#pragma unroll 4
        for (int i = 0; i < 32; i++) {
            int row = r0 + i;
            int gg = sG[row];
            if (gg != cg) {
                if (cg >= 0) atomicAdd(&pooledf[cg * HIDC + col], run);
                run = 0.f; cg = gg;
            }
            run += sD[row * SAS + col];
        }
        if (cg >= 0) atomicAdd(&pooledf[cg * HIDC + col], run);
    }
}

// ---------------- classifier ----------------
__global__ void k_cls(const float* __restrict__ Wc, const float* __restrict__ bc,
                      float* __restrict__ out) {
    __shared__ float sp[HIDC];
    int g = blockIdx.x, t = threadIdx.x;   // 32 threads
    float bias = (t < NCLS) ? __ldg(&bc[t]) : 0.f;   // pre-wait
    gdc_wait();
    float invg = 1.0f / fmaxf(g_gcnt[g], 1.0f);
    const float* pooledf = (const float*)g_pooled;
    sp[t] = pooledf[g * HIDC + t] * invg;
    sp[t + 32] = pooledf[g * HIDC + 32 + t] * invg;
    __syncwarp();
    if (t < NCLS) {
        float a = bias;
#pragma unroll
        for (int j = 0; j < HIDC; j++) a += sp[j] * __ldg(&Wc[j * NCLS + t]);
        out[g * NCLS + t] = a;
    }
}

// ---------------- launch helpers (PDL) ----------------
template <typename... Args>
static void launch_pdl(void (*fn)(Args...), dim3 grid, dim3 block, Args... args) {
    cudaLaunchConfig_t cfg = {};
    cfg.gridDim = grid;
    cfg.blockDim = block;
    cfg.dynamicSmemBytes = 0;
    cfg.stream = 0;
    cudaLaunchAttribute at[1];
    at[0].id = cudaLaunchAttributeProgrammaticStreamSerialization;
    at[0].val.programmaticStreamSerializationAllowed = 1;
    cfg.attrs = at;
    cfg.numAttrs = 1;
    cudaLaunchKernelEx(&cfg, fn, args...);
}

extern "C" void kernel_launch(void* const* d_in, const int* in_sizes, int n_in,
                              void* d_out, int out_size) {
    const float* x   = (const float*)d_in[0];
    const void*  ei  = d_in[1];
    const void*  bt  = d_in[2];
    const float* W1l = (const float*)d_in[3];
    const float* b1  = (const float*)d_in[4];
    const float* W1r = (const float*)d_in[5];
    const float* W2l = (const float*)d_in[6];
    const float* b2  = (const float*)d_in[7];
    const float* W2r = (const float*)d_in[8];
    const float* Wc  = (const float*)d_in[9];
    const float* bc  = (const float*)d_in[10];
    float* out = (float*)d_out;

    k_scatter<<<N_EDGESC / 1024, 256>>>(ei, x);
    launch_pdl(k_s1, dim3((N_NODESC + 255) / 256), dim3(256), x, (const void*)bt);
    launch_pdl(k_sweep2, dim3(N_NODESC / 8), dim3(256), W1l, b1, W1r);
    launch_pdl(k_h2pool, dim3(H2_BLKS), dim3(128), (const void*)bt, W1l, b1, W1r, W2l, b2, W2r);
    launch_pdl(k_cls, dim3(N_GRAPHSC), dim3(32), Wc, bc, out);
}